// round 5
// baseline (speedup 1.0000x reference)
#include <cuda_runtime.h>

#define BATCH  4
#define CIN    256
#define NHW    2304      // 48*48
#define HEADS  8
#define DH     64
#define INNER  512       // HEADS*DH

// ---------------- scratch (static device arrays; no allocs allowed) -------
__device__ float g_q[(size_t)BATCH * HEADS * NHW * DH];
__device__ float g_k[(size_t)BATCH * HEADS * NHW * DH];
__device__ float g_v[(size_t)BATCH * HEADS * NHW * DH];
__device__ float g_a[(size_t)BATCH * INNER * NHW];   // attention out, [b][c=512][n]

// ===========================================================================
// Kernel 1: QKV projection. qkv[b,o,n] = sum_c w[o,c] * x[b,c,n]
// grid (24, NHW/64, B), block 256. Each block: 64 o x 64 n tile.
// Tile seg: 0..7 -> q head, 8..15 -> k head, 16..23 -> v head.
// Writes to buf[((b*H+h)*N + n)*64 + d] (d contiguous).
// ===========================================================================
__global__ __launch_bounds__(256) void qkv_gemm_kernel(
    const float* __restrict__ x, const float* __restrict__ w)
{
    __shared__ float sW[16][68];  // k-major: sW[k][o]
    __shared__ float sX[16][68];  // sX[k][n]

    const int t  = threadIdx.x;
    const int tx = t & 15, ty = t >> 4;
    const int seg = blockIdx.x;
    const int o0  = seg * 64;
    const int n0  = blockIdx.y * 64;
    const int b   = blockIdx.z;
    const float* xb = x + (size_t)b * CIN * NHW;

    float acc[4][4] = {};

    for (int k0 = 0; k0 < CIN; k0 += 16) {
        {   // W tile: 64 o x 16 k, stored transposed
            int oo = t >> 2;
            int kc = (t & 3) * 4;
            float4 wv = *reinterpret_cast<const float4*>(&w[(size_t)(o0 + oo) * CIN + k0 + kc]);
            sW[kc + 0][oo] = wv.x; sW[kc + 1][oo] = wv.y;
            sW[kc + 2][oo] = wv.z; sW[kc + 3][oo] = wv.w;
        }
        {   // X tile: 16 k x 64 n
            int kk = t >> 4;
            int nc = (t & 15) * 4;
            *reinterpret_cast<float4*>(&sX[kk][nc]) =
                *reinterpret_cast<const float4*>(&xb[(size_t)(k0 + kk) * NHW + n0 + nc]);
        }
        __syncthreads();
#pragma unroll
        for (int kk = 0; kk < 16; kk++) {
            float4 a4 = *reinterpret_cast<const float4*>(&sW[kk][ty * 4]);
            float4 b4 = *reinterpret_cast<const float4*>(&sX[kk][tx * 4]);
            float av[4] = {a4.x, a4.y, a4.z, a4.w};
            float bv[4] = {b4.x, b4.y, b4.z, b4.w};
#pragma unroll
            for (int i = 0; i < 4; i++)
#pragma unroll
                for (int j = 0; j < 4; j++)
                    acc[i][j] = fmaf(av[i], bv[j], acc[i][j]);
        }
        __syncthreads();
    }

    float* dst = (seg < 8) ? g_q : (seg < 16) ? g_k : g_v;
    const int h = seg & 7;
    // d = ty*4 + i (o within head), n = n0 + tx*4 + j
    size_t base = ((size_t)(b * HEADS + h) * NHW + n0 + tx * 4) * DH + ty * 4;
#pragma unroll
    for (int j = 0; j < 4; j++) {
        float4 o4 = make_float4(acc[0][j], acc[1][j], acc[2][j], acc[3][j]);
        *reinterpret_cast<float4*>(&dst[base + (size_t)j * DH]) = o4;
    }
}

// ===========================================================================
// Kernel 2: L2 normalize rows of 64 (q gets SCALE=10 folded in, k gets 1.0)
// grid ((B*H*N)/8, 2), block 256 (8 warps, one row per warp)
// ===========================================================================
__global__ __launch_bounds__(256) void l2norm_kernel()
{
    float* buf = (blockIdx.y == 0) ? g_q : g_k;
    const float mul = (blockIdx.y == 0) ? 10.0f : 1.0f;
    const size_t row = (size_t)blockIdx.x * 8 + (threadIdx.x >> 5);
    const int lane = threadIdx.x & 31;

    float2 v = *reinterpret_cast<float2*>(&buf[row * DH + lane * 2]);
    float s = v.x * v.x + v.y * v.y;
#pragma unroll
    for (int off = 16; off > 0; off >>= 1)
        s += __shfl_xor_sync(0xffffffffu, s, off);
    float sc = mul / fmaxf(sqrtf(s), 1e-12f);
    v.x *= sc; v.y *= sc;
    *reinterpret_cast<float2*>(&buf[row * DH + lane * 2]) = v;
}

// ===========================================================================
// Kernel 3: flash attention, fp32. grid (NHW/64, HEADS, B), block 256.
// smem: sQt[kk][r] (k-major Q tile), sKt[kk][c] (k-major K tile, reused as
// Pt[kk][r] for the PV GEMM), sV[kv][d]. stride 68 keeps float4 alignment
// and conflict-free inner-loop LDS.128.
// ===========================================================================
#define SM_STRIDE 68
#define ATT_SMEM  (3 * 64 * SM_STRIDE * 4)

__global__ __launch_bounds__(256) void attn_kernel()
{
    extern __shared__ float sm[];
    float (*sQt)[SM_STRIDE] = reinterpret_cast<float(*)[SM_STRIDE]>(sm);
    float (*sKt)[SM_STRIDE] = reinterpret_cast<float(*)[SM_STRIDE]>(sm + 64 * SM_STRIDE);
    float (*sV )[SM_STRIDE] = reinterpret_cast<float(*)[SM_STRIDE]>(sm + 2 * 64 * SM_STRIDE);

    const int t  = threadIdx.x;
    const int tx = t & 15, ty = t >> 4;
    const int qt = blockIdx.x, h = blockIdx.y, b = blockIdx.z;
    const size_t bh = (size_t)(b * HEADS + h) * NHW;
    const float* qg = g_q + (bh + (size_t)qt * 64) * DH;
    const float* kg = g_k + bh * DH;
    const float* vg = g_v + bh * DH;

    // Load Q tile transposed: sQt[kk][r] = Q[r][kk]
#pragma unroll
    for (int p = 0; p < 4; p++) {
        int r  = t >> 2;
        int kc = (t & 3) * 4 + p * 16;
        float4 q4 = *reinterpret_cast<const float4*>(&qg[(size_t)r * DH + kc]);
        sQt[kc + 0][r] = q4.x; sQt[kc + 1][r] = q4.y;
        sQt[kc + 2][r] = q4.z; sQt[kc + 3][r] = q4.w;
    }

    float o_acc[4][4] = {};
    float m_run[4], l_run[4];
#pragma unroll
    for (int i = 0; i < 4; i++) { m_run[i] = -1e30f; l_run[i] = 0.0f; }

    __syncthreads();

    for (int kv0 = 0; kv0 < NHW; kv0 += 64) {
        // K tile transposed + V tile natural
#pragma unroll
        for (int p = 0; p < 4; p++) {
            int r  = t >> 2;
            int kc = (t & 3) * 4 + p * 16;
            float4 k4 = *reinterpret_cast<const float4*>(&kg[(size_t)(kv0 + r) * DH + kc]);
            sKt[kc + 0][r] = k4.x; sKt[kc + 1][r] = k4.y;
            sKt[kc + 2][r] = k4.z; sKt[kc + 3][r] = k4.w;
        }
#pragma unroll
        for (int p = 0; p < 4; p++) {
            int rr = (t >> 4) + p * 16;
            int dc = (t & 15) * 4;
            *reinterpret_cast<float4*>(&sV[rr][dc]) =
                *reinterpret_cast<const float4*>(&vg[(size_t)(kv0 + rr) * DH + dc]);
        }
        __syncthreads();

        // GEMM1: S[r][c] = sum_kk Q[r][kk]*K[c][kk]   (scale folded into Q)
        float s[4][4] = {};
#pragma unroll 16
        for (int kk = 0; kk < 64; kk++) {
            float4 q4 = *reinterpret_cast<const float4*>(&sQt[kk][ty * 4]);
            float4 k4 = *reinterpret_cast<const float4*>(&sKt[kk][tx * 4]);
            float qv[4] = {q4.x, q4.y, q4.z, q4.w};
            float kv[4] = {k4.x, k4.y, k4.z, k4.w};
#pragma unroll
            for (int i = 0; i < 4; i++)
#pragma unroll
                for (int j = 0; j < 4; j++)
                    s[i][j] = fmaf(qv[i], kv[j], s[i][j]);
        }

        // online softmax (row r handled by 16 lanes in a half-warp)
        float p[4][4];
#pragma unroll
        for (int i = 0; i < 4; i++) {
            float ml = fmaxf(fmaxf(s[i][0], s[i][1]), fmaxf(s[i][2], s[i][3]));
#pragma unroll
            for (int off = 8; off > 0; off >>= 1)
                ml = fmaxf(ml, __shfl_xor_sync(0xffffffffu, ml, off));
            float mnew = fmaxf(m_run[i], ml);
            float corr = __expf(m_run[i] - mnew);
            l_run[i] *= corr;
#pragma unroll
            for (int j = 0; j < 4; j++) o_acc[i][j] *= corr;
            float ls = 0.0f;
#pragma unroll
            for (int j = 0; j < 4; j++) {
                p[i][j] = __expf(s[i][j] - mnew);
                ls += p[i][j];
            }
#pragma unroll
            for (int off = 8; off > 0; off >>= 1)
                ls += __shfl_xor_sync(0xffffffffu, ls, off);
            l_run[i] += ls;
            m_run[i] = mnew;
        }

        __syncthreads();   // all GEMM1 reads of sKt done
        // write P transposed into sKt: Pt[c][r]
#pragma unroll
        for (int i = 0; i < 4; i++)
#pragma unroll
            for (int j = 0; j < 4; j++)
                sKt[tx * 4 + j][ty * 4 + i] = p[i][j];
        __syncthreads();

        // GEMM2: O[r][d] += P[r][kk]*V[kk][d]
#pragma unroll 16
        for (int kk = 0; kk < 64; kk++) {
            float4 p4 = *reinterpret_cast<const float4*>(&sKt[kk][ty * 4]);
            float4 v4 = *reinterpret_cast<const float4*>(&sV[kk][tx * 4]);
            float pv[4] = {p4.x, p4.y, p4.z, p4.w};
            float vv[4] = {v4.x, v4.y, v4.z, v4.w};
#pragma unroll
            for (int i = 0; i < 4; i++)
#pragma unroll
                for (int j = 0; j < 4; j++)
                    o_acc[i][j] = fmaf(pv[i], vv[j], o_acc[i][j]);
        }
        __syncthreads();   // done with sKt/sV before next tile's loads
    }

    // epilogue: divide by l, store transposed into g_a[b][h*64+d][n]
#pragma unroll
    for (int i = 0; i < 4; i++) {
        float inv = 1.0f / l_run[i];
#pragma unroll
        for (int j = 0; j < 4; j++) o_acc[i][j] *= inv;
    }
    size_t cbase = ((size_t)b * INNER + h * 64 + tx * 4) * NHW + (size_t)qt * 64 + ty * 4;
#pragma unroll
    for (int j = 0; j < 4; j++) {
        float4 o4 = make_float4(o_acc[0][j], o_acc[1][j], o_acc[2][j], o_acc[3][j]);
        *reinterpret_cast<float4*>(&g_a[cbase + (size_t)j * NHW]) = o4;
    }
}

// ===========================================================================
// Kernel 4: output projection. y[b,o,n] = sum_c w_out[o,c]*a[b,c,n] + bias[o]
// grid (CIN/64, NHW/64, B), block 256.
// ===========================================================================
__global__ __launch_bounds__(256) void out_gemm_kernel(
    const float* __restrict__ w, const float* __restrict__ bias,
    float* __restrict__ y)
{
    __shared__ float sW[16][68];
    __shared__ float sA[16][68];

    const int t  = threadIdx.x;
    const int tx = t & 15, ty = t >> 4;
    const int o0 = blockIdx.x * 64;
    const int n0 = blockIdx.y * 64;
    const int b  = blockIdx.z;
    const float* ab = g_a + (size_t)b * INNER * NHW;

    float acc[4][4] = {};

    for (int k0 = 0; k0 < INNER; k0 += 16) {
        {
            int oo = t >> 2;
            int kc = (t & 3) * 4;
            float4 wv = *reinterpret_cast<const float4*>(&w[(size_t)(o0 + oo) * INNER + k0 + kc]);
            sW[kc + 0][oo] = wv.x; sW[kc + 1][oo] = wv.y;
            sW[kc + 2][oo] = wv.z; sW[kc + 3][oo] = wv.w;
        }
        {
            int kk = t >> 4;
            int nc = (t & 15) * 4;
            *reinterpret_cast<float4*>(&sA[kk][nc]) =
                *reinterpret_cast<const float4*>(&ab[(size_t)(k0 + kk) * NHW + n0 + nc]);
        }
        __syncthreads();
#pragma unroll
        for (int kk = 0; kk < 16; kk++) {
            float4 a4 = *reinterpret_cast<const float4*>(&sW[kk][ty * 4]);
            float4 b4 = *reinterpret_cast<const float4*>(&sA[kk][tx * 4]);
            float av[4] = {a4.x, a4.y, a4.z, a4.w};
            float bv[4] = {b4.x, b4.y, b4.z, b4.w};
#pragma unroll
            for (int i = 0; i < 4; i++)
#pragma unroll
                for (int j = 0; j < 4; j++)
                    acc[i][j] = fmaf(av[i], bv[j], acc[i][j]);
        }
        __syncthreads();
    }

    const int o = o0 + ty * 4;
    size_t base = ((size_t)b * CIN + o) * NHW + n0 + tx * 4;
#pragma unroll
    for (int i = 0; i < 4; i++) {
        float bi = bias[o + i];
        float4 r = make_float4(acc[i][0] + bi, acc[i][1] + bi,
                               acc[i][2] + bi, acc[i][3] + bi);
        *reinterpret_cast<float4*>(&y[base + (size_t)i * NHW]) = r;
    }
}

// ===========================================================================
extern "C" void kernel_launch(void* const* d_in, const int* in_sizes, int n_in,
                              void* d_out, int out_size)
{
    const float* x     = (const float*)d_in[0];
    const float* w_qkv = (const float*)d_in[1];
    const float* w_out = (const float*)d_in[2];
    const float* b_out = (const float*)d_in[3];
    float* y = (float*)d_out;

    cudaFuncSetAttribute(attn_kernel,
                         cudaFuncAttributeMaxDynamicSharedMemorySize, ATT_SMEM);

    qkv_gemm_kernel<<<dim3(24, NHW / 64, BATCH), 256>>>(x, w_qkv);
    l2norm_kernel<<<dim3((BATCH * HEADS * NHW) / 8, 2), 256>>>();
    attn_kernel<<<dim3(NHW / 64, HEADS, BATCH), 256, ATT_SMEM>>>();
    out_gemm_kernel<<<dim3(CIN / 64, NHW / 64, BATCH), 256>>>(w_out, b_out, y);
}